// round 2
// baseline (speedup 1.0000x reference)
#include <cuda_runtime.h>

#define N_NODES 100000
#define E_EDGES 3200000
#define F 64
#define F4 16

// Scratch (allocation-free rule: __device__ globals)
__device__ float g_buf1[N_NODES * F];   // hs1, then a1 (relu output)
__device__ float g_buf2[N_NODES * F];   // acc1, then hs2
__device__ float g_dinv[N_NODES];
__device__ int   g_cnt[N_NODES];

__global__ void k_init_cnt() {
    int i = blockIdx.x * blockDim.x + threadIdx.x;
    if (i < N_NODES) g_cnt[i] = 1;   // self-loop
}

__global__ void k_count(const int* __restrict__ dst) {
    int e = blockIdx.x * blockDim.x + threadIdx.x;
    if (e < E_EDGES) atomicAdd(&g_cnt[dst[e]], 1);
}

__global__ void k_dinv() {
    int i = blockIdx.x * blockDim.x + threadIdx.x;
    if (i < N_NODES) g_dinv[i] = rsqrtf((float)g_cnt[i]);
}

// One thread per row: acc[64] in registers, W staged in shared memory,
// epilogue scales the whole row by dinv[row].
template<int K>
__global__ __launch_bounds__(128)
void k_gemm_scale(const float* __restrict__ X,
                  const float* __restrict__ W,
                  float* __restrict__ out) {
    __shared__ float4 Ws[K * F4];
    for (int t = threadIdx.x; t < K * F4; t += 128)
        Ws[t] = reinterpret_cast<const float4*>(W)[t];
    __syncthreads();

    int row = blockIdx.x * 128 + threadIdx.x;
    if (row >= N_NODES) return;

    float acc[F];
#pragma unroll
    for (int j = 0; j < F; j++) acc[j] = 0.f;

    const float4* xr = reinterpret_cast<const float4*>(X + (size_t)row * K);
#pragma unroll 2
    for (int k4 = 0; k4 < K / 4; k4++) {
        float4 xv = xr[k4];
        float xs[4] = {xv.x, xv.y, xv.z, xv.w};
#pragma unroll
        for (int kk = 0; kk < 4; kk++) {
            float xk = xs[kk];
#pragma unroll
            for (int j4 = 0; j4 < F4; j4++) {
                float4 w = Ws[(k4 * 4 + kk) * F4 + j4];
                acc[j4 * 4 + 0] += xk * w.x;
                acc[j4 * 4 + 1] += xk * w.y;
                acc[j4 * 4 + 2] += xk * w.z;
                acc[j4 * 4 + 3] += xk * w.w;
            }
        }
    }

    float s = g_dinv[row];
    float4* o = reinterpret_cast<float4*>(out + (size_t)row * F);
#pragma unroll
    for (int j4 = 0; j4 < F4; j4++) {
        float4 v;
        v.x = acc[j4 * 4 + 0] * s;
        v.y = acc[j4 * 4 + 1] * s;
        v.z = acc[j4 * 4 + 2] * s;
        v.w = acc[j4 * 4 + 3] * s;
        o[j4] = v;
    }
}

__global__ void k_zero(float4* __restrict__ p, int n4) {
    int i = blockIdx.x * blockDim.x + threadIdx.x;
    if (i < n4) p[i] = make_float4(0.f, 0.f, 0.f, 0.f);
}

// 16 threads per edge, each RED.v4 one 16B chunk of the 256B feature row.
__global__ void k_scatter(const int* __restrict__ src,
                          const int* __restrict__ dst,
                          const float4* __restrict__ hs,
                          float4* __restrict__ acc) {
    int idx = blockIdx.x * blockDim.x + threadIdx.x;
    if (idx >= E_EDGES * 16) return;
    int e = idx >> 4;
    int c = idx & 15;
    int s = __ldg(&src[e]);
    int d = __ldg(&dst[e]);
    float4 v = hs[s * 16 + c];
    asm volatile("red.global.add.v4.f32 [%0], {%1, %2, %3, %4};"
                 :: "l"(acc + d * 16 + c),
                    "f"(v.x), "f"(v.y), "f"(v.z), "f"(v.w)
                 : "memory");
}

// out[row] = dinv[row]*(acc[row] + hs[row]) + bias  (+ optional relu)
// Safe to alias outv with accv or hsv (per-element read-then-write).
template<bool RELU>
__global__ void k_finalize(const float4* __restrict__ accv,
                           const float4* __restrict__ hsv,
                           const float* __restrict__ bias,
                           float4* __restrict__ outv) {
    int idx = blockIdx.x * blockDim.x + threadIdx.x;
    if (idx >= N_NODES * F4) return;
    int row = idx >> 4;
    int c = idx & 15;
    float s = g_dinv[row];
    float4 a = accv[idx];
    float4 h = hsv[idx];
    float4 b = reinterpret_cast<const float4*>(bias)[c];
    float4 r;
    r.x = fmaf(s, a.x + h.x, b.x);
    r.y = fmaf(s, a.y + h.y, b.y);
    r.z = fmaf(s, a.z + h.z, b.z);
    r.w = fmaf(s, a.w + h.w, b.w);
    if (RELU) {
        r.x = fmaxf(r.x, 0.f);
        r.y = fmaxf(r.y, 0.f);
        r.z = fmaxf(r.z, 0.f);
        r.w = fmaxf(r.w, 0.f);
    }
    outv[idx] = r;
}

extern "C" void kernel_launch(void* const* d_in, const int* in_sizes, int n_in,
                              void* d_out, int out_size) {
    const float* x   = (const float*)d_in[0];
    const int*   src = (const int*)d_in[1];            // edge_index row 0
    const int*   dst = (const int*)d_in[1] + E_EDGES;  // edge_index row 1
    const float* W1  = (const float*)d_in[2];
    const float* b1  = (const float*)d_in[3];
    const float* W2  = (const float*)d_in[4];
    const float* b2  = (const float*)d_in[5];
    float* out = (float*)d_out;

    float *buf1 = nullptr, *buf2 = nullptr;
    cudaGetSymbolAddress((void**)&buf1, g_buf1);
    cudaGetSymbolAddress((void**)&buf2, g_buf2);

    const int TB = 256;
    const int nb_nodes = (N_NODES + TB - 1) / TB;
    const int nb_edges = (E_EDGES + TB - 1) / TB;
    const int nv4      = N_NODES * F4;
    const int nb_feat  = (nv4 + TB - 1) / TB;
    const int nb_scat  = (E_EDGES * 16 + TB - 1) / TB;
    const int nb_gemm  = (N_NODES + 127) / 128;

    // degrees + dinv
    k_init_cnt<<<nb_nodes, TB>>>();
    k_count<<<nb_edges, TB>>>(dst);
    k_dinv<<<nb_nodes, TB>>>();

    // Layer 1: hs1 = (x @ W1) * dinv
    k_gemm_scale<128><<<nb_gemm, 128>>>(x, W1, buf1);
    k_zero<<<nb_feat, TB>>>((float4*)buf2, nv4);
    k_scatter<<<nb_scat, TB>>>(src, dst, (const float4*)buf1, (float4*)buf2);
    // a1 = relu(dinv*(acc1 + hs1) + b1)  -> overwrite buf1
    k_finalize<true><<<nb_feat, TB>>>((const float4*)buf2, (const float4*)buf1,
                                      b1, (float4*)buf1);

    // Layer 2: hs2 = (a1 @ W2) * dinv  -> buf2
    k_gemm_scale<64><<<nb_gemm, 128>>>(buf1, W2, buf2);
    k_zero<<<nb_feat, TB>>>((float4*)out, nv4);
    k_scatter<<<nb_scat, TB>>>(src, dst, (const float4*)buf2, (float4*)out);
    // out = dinv*(acc2 + hs2) + b2  (no relu) -> in place on d_out
    k_finalize<false><<<nb_feat, TB>>>((const float4*)out, (const float4*)buf2,
                                       b2, (float4*)out);
}